// round 16
// baseline (speedup 1.0000x reference)
#include <cuda_runtime.h>

// Problem shape (fixed): x_hr (16,3,512,512) f32, w1 (3,9) f32.
#define BB 16
#define HH 512
#define WW 512
#define HW (HH*WW)
#define NPIX (BB*HW)
#define NT 512

// Per-pixel scratch maps (__device__ globals allowed).
__device__ float2 g_uv[NPIX];   // (sum_c x, sum_c x^2)
__device__ float2 g_P1[NPIX];   // cumulative affine after stage 1: F1 = P.x*x + P.y
__device__ float2 g_P2[NPIX];   // cumulative affine after stage 2
__constant__ float cw[27];      // 1x1 conv weights (3x9)

// ---- packed fp32x2 helpers (sm_103a): one instruction for both components ----
__device__ __forceinline__ float2 p_add(float2 a, float2 b) {
    float2 r;
    asm("{\n\t.reg .b64 x, y, z;\n\t"
        "mov.b64 x, {%2, %3};\n\t"
        "mov.b64 y, {%4, %5};\n\t"
        "add.rn.f32x2 z, x, y;\n\t"
        "mov.b64 {%0, %1}, z;\n\t}"
        : "=f"(r.x), "=f"(r.y)
        : "f"(a.x), "f"(a.y), "f"(b.x), "f"(b.y));
    return r;
}
// acc + (vi - vo), both lanes packed: 2 f32x2 ops instead of 4 scalar.
__device__ __forceinline__ float2 p_slide(float2 acc, float2 vi, float2 vo) {
    float2 r;
    asm("{\n\t.reg .b64 a, i, o, d, z;\n\t"
        "mov.b64 a, {%2, %3};\n\t"
        "mov.b64 i, {%4, %5};\n\t"
        "mov.b64 o, {%6, %7};\n\t"
        "sub.rn.f32x2 d, i, o;\n\t"
        "add.rn.f32x2 z, a, d;\n\t"
        "mov.b64 {%0, %1}, z;\n\t}"
        : "=f"(r.x), "=f"(r.y)
        : "f"(acc.x), "f"(acc.y), "f"(vi.x), "f"(vi.y), "f"(vo.x), "f"(vo.y));
    return r;
}

// ---------------- stage 1: fully staged, fixed-trip ring slides ----------------
__global__ void __launch_bounds__(NT, 3) stage1_kernel(const float* __restrict__ x) {
    constexpr int R = 1, T = 64;
    constexpr int K  = 2 * R + 1;
    constexpr int E1 = T + 2 * R;    // 66
    constexpr int E2 = T + 4 * R;    // 68
    constexpr int SP = E2 + 1;
    constexpr int HP = E1 + 1;
    constexpr float EPS = 0.16f;

    constexpr int NS1 = NT / E2, LS1 = (E1 + NS1 - 1) / NS1;
    constexpr int NV1 = NT / E1, LV1 = (E1 + NV1 - 1) / NV1;
    constexpr int NS2 = NT / E1, LS2 = (T + NS2 - 1) / NS2;
    constexpr int NV2 = NT / T,  LV2 = T / NV2;

    extern __shared__ float2 sm2[];
    float2* SS = sm2;                    // E2 x SP (s), later (A,b)
    float2* Hs = SS + E2 * SP;           // E2 x HP
    float*  ry = (float*)(Hs + E2 * HP); // E1 row factors

    const int tid = threadIdx.x;
    const int gx0 = blockIdx.x * T, gy0 = blockIdx.y * T;
    const int b = blockIdx.z, gb = b * HW;

    if (tid < E1) {
        int gy = gy0 - R + tid;
        float r = 0.f;
        if ((unsigned)gy < (unsigned)HH)
            r = __frcp_rn((float)(min(gy + R, HH - 1) - max(gy - R, 0) + 1));
        ry[tid] = r;
    }

    // P0: load x once; build s = (sum_c x, sum_c x^2); persist uv for interior
    for (int idx = tid; idx < E2 * E2; idx += NT) {
        int iy = idx / E2, ix = idx - iy * E2;
        int gy = gy0 - 2 * R + iy, gx = gx0 - 2 * R + ix;
        float2 s = make_float2(0.f, 0.f);
        if ((unsigned)gy < (unsigned)HH && (unsigned)gx < (unsigned)WW) {
            const float* xb = x + (size_t)b * 3 * HW + gy * WW + gx;
            float x0 = xb[0], x1 = xb[HW], x2 = xb[2 * HW];
            s.x = x0 + x1 + x2;
            s.y = x0 * x0 + x1 * x1 + x2 * x2;
            if (iy >= 2 * R && iy < 2 * R + T && ix >= 2 * R && ix < 2 * R + T)
                g_uv[gb + gy * WW + gx] = s;
        }
        SS[iy * SP + ix] = s;
    }
    __syncthreads();

    // P1: horizontal box (fixed LS1 trips, ring sub-side)
    for (int item = tid; item < E2 * NS1; item += NT) {
        int r = item % E2, seg = item / E2;
        int c0 = seg * LS1; if (c0 > E1 - LS1) c0 = E1 - LS1;
        const float2* p = SS + r * SP;
        float2* o = Hs + r * HP;
        float2 ring[K];
        float2 acc = make_float2(0.f, 0.f);
#pragma unroll
        for (int j = 0; j < K; ++j) { float2 v = p[c0 + j]; ring[j] = v; acc = p_add(acc, v); }
        o[c0] = acc;
#pragma unroll
        for (int k = 1; k < LS1; ++k) {
            float2 vi = p[c0 + k + K - 1];
            float2 vo = ring[(k - 1) % K];
            ring[(k - 1) % K] = vi;
            acc = p_slide(acc, vi, vo);
            o[c0 + k] = acc;
        }
    }
    __syncthreads();

    // P2: vertical box + pointwise (A,b) -> SS (fixed LV1 trips, ring)
    for (int item = tid; item < E1 * NV1; item += NT) {
        int c = item % E1, seg = item / E1;
        int r0 = seg * LV1; if (r0 > E1 - LV1) r0 = E1 - LV1;
        int gx = gx0 - R + c;
        float rx = 0.f;
        if ((unsigned)gx < (unsigned)WW)
            rx = __frcp_rn(3.f * (float)(min(gx + R, WW - 1) - max(gx - R, 0) + 1));
        float2 ring[K];
        float2 acc = make_float2(0.f, 0.f);
#pragma unroll
        for (int j = 0; j < K; ++j) { float2 v = Hs[(r0 + j) * HP + c]; ring[j] = v; acc = p_add(acc, v); }
#pragma unroll
        for (int k = 0; k < LV1; ++k) {
            if (k > 0) {
                float2 vi = Hs[(r0 + k + K - 1) * HP + c];
                float2 vo = ring[(k - 1) % K];
                ring[(k - 1) % K] = vi;
                acc = p_slide(acc, vi, vo);
            }
            float inv = ry[r0 + k] * rx;
            float m = acc.x * inv, q = acc.y * inv;
            float var = fmaf(-m, m, q);
            float rr = __frcp_rn(var + EPS);
            SS[(r0 + k) * SP + c] = make_float2(var * rr, m * (EPS * rr));
        }
    }
    __syncthreads();

    // P3: horizontal box of (A,b) (fixed LS2 trips, ring)
    for (int item = tid; item < E1 * NS2; item += NT) {
        int r = item % E1, seg = item / E1;
        int c0 = seg * LS2; if (c0 > T - LS2) c0 = T - LS2;
        const float2* p = SS + r * SP;
        float2* o = Hs + r * HP;
        float2 ring[K];
        float2 acc = make_float2(0.f, 0.f);
#pragma unroll
        for (int j = 0; j < K; ++j) { float2 v = p[c0 + j]; ring[j] = v; acc = p_add(acc, v); }
        o[c0] = acc;
#pragma unroll
        for (int k = 1; k < LS2; ++k) {
            float2 vi = p[c0 + k + K - 1];
            float2 vo = ring[(k - 1) % K];
            ring[(k - 1) % K] = vi;
            acc = p_slide(acc, vi, vo);
            o[c0 + k] = acc;
        }
    }
    __syncthreads();

    // P4: vertical box + epilogue -> g_P1 (fixed LV2 trips, ring)
    for (int item = tid; item < T * NV2; item += NT) {
        int c = item % T, seg = item / T;
        int r0 = seg * LV2;
        int gx = gx0 + c;
        float2 ring[K];
        float2 acc = make_float2(0.f, 0.f);
#pragma unroll
        for (int j = 0; j < K; ++j) { float2 v = Hs[(r0 + j) * HP + c]; ring[j] = v; acc = p_add(acc, v); }
#pragma unroll
        for (int k = 0; k < LV2; ++k) {
            if (k > 0) {
                float2 vi = Hs[(r0 + k + K - 1) * HP + c];
                float2 vo = ring[(k - 1) % K];
                ring[(k - 1) % K] = vi;
                acc = p_slide(acc, vi, vo);
            }
            g_P1[gb + (gy0 + r0 + k) * WW + gx] = make_float2(3.f * acc.x, 3.f * acc.y);
        }
    }
}

// Channel-sum eval from (u,v) + cumulative affine (two LDG.64).
template <int STAGE>
__device__ __forceinline__ float2 s_eval(int gb, int gy, int gx, bool vx) {
    if (!vx || (unsigned)gy >= (unsigned)HH) return make_float2(0.f, 0.f);
    int g = gb + gy * WW + gx;
    float2 uv = g_uv[g];
    float2 P  = (STAGE == 2) ? g_P1[g] : g_P2[g];
    return make_float2(fmaf(P.x, uv.x, 3.f * P.y),
                       fmaf(P.x * P.x, uv.y,
                            fmaf(2.f * P.x * P.y, uv.x, 3.f * P.y * P.y)));
}

// ---------------- stages 2 & 3: 4 phases; rings + packed slides ----------------
template <int R, int STAGE, int T, int MINB>
__global__ void __launch_bounds__(NT, MINB) gf_kernel(const float* __restrict__ x,
                                                      float* __restrict__ out) {
    constexpr int K   = 2 * R + 1;
    constexpr int H1R = T + 2 * R;
    constexpr int W2  = T + 2 * R;
    constexpr int W1  = T + 4 * R;
    constexpr int P1W = W1 + 1;
    constexpr int ABW = W2 + 1;
    constexpr int GW  = T + 1;
    constexpr float EPS = (STAGE == 2) ? 0.04f : 0.01f;

    constexpr int NSEG1 = NT / W1,  LR1 = (H1R + NSEG1 - 1) / NSEG1;
    constexpr int NSEG2 = NT / H1R, LC2 = (W2 + NSEG2 - 1) / NSEG2;
    constexpr int NSEG3 = NT / H1R, LC3 = (T + NSEG3 - 1) / NSEG3;
    constexpr int NSEG4 = NT / T,   LR4 = (T + NSEG4 - 1) / NSEG4;
    static_assert(H1R >= LR1 && W2 >= LC2 && T >= LC3 && T >= LR4, "clamp ok");
    static_assert(LR4 - 1 <= K, "P4 head-cache covers all subtract indices");

    extern __shared__ float2 sm2[];
    float2* V1 = sm2;                    // H1R x P1W
    float2* AB = V1 + H1R * P1W;         // H1R x ABW
    float2* G  = V1;                     // aliases dead V1 after P2
    float*  rx = (float*)(AB + H1R * ABW);
    float*  ry = rx + W2;

    const int tid = threadIdx.x;
    const int gx0 = blockIdx.x * T, gy0 = blockIdx.y * T;
    const int b = blockIdx.z, gb = b * HW;

    if (tid < W2) {
        int gx = gx0 - R + tid;
        float v = 0.f;
        if ((unsigned)gx < (unsigned)WW)
            v = __frcp_rn((float)(min(gx + R, WW - 1) - max(gx - R, 0) + 1));
        rx[tid] = v;
    }
    int t2 = tid - 128;
    if (t2 >= 0 && t2 < H1R) {
        int gy = gy0 - R + t2;
        float v = 0.f;
        if ((unsigned)gy < (unsigned)HH)
            v = __frcp_rn(3.f * (float)(min(gy + R, HH - 1) - max(gy - R, 0) + 1));
        ry[t2] = v;
    }

    // P1: vertical box of s off global, register-ring slide (fixed LR1 trips)
    for (int item = tid; item < W1 * NSEG1; item += NT) {
        int c = item % W1, seg = item / W1;
        int r0 = seg * LR1; if (r0 > H1R - LR1) r0 = H1R - LR1;
        int gx = gx0 - 2 * R + c;
        bool vx = (unsigned)gx < (unsigned)WW;
        int ybase = gy0 - 2 * R + r0;
        float2 ring[K];
        float2 acc = make_float2(0.f, 0.f);
#pragma unroll
        for (int j = 0; j < K; ++j) {
            float2 s = s_eval<STAGE>(gb, ybase + j, gx, vx);
            ring[j] = s;
            acc = p_add(acc, s);
        }
        V1[r0 * P1W + c] = acc;
#pragma unroll
        for (int k = 1; k < LR1; ++k) {
            float2 sa = s_eval<STAGE>(gb, ybase + k + K - 1, gx, vx);
            float2 sb = ring[(k - 1) % K];
            ring[(k - 1) % K] = sa;
            acc = p_slide(acc, sa, sb);
            V1[(r0 + k) * P1W + c] = acc;
        }
    }
    __syncthreads();

    // P2: horizontal box + pointwise (A,b) (fixed LC2 trips, ring)
    for (int item = tid; item < H1R * NSEG2; item += NT) {
        int r = item % H1R, seg = item / H1R;
        int c0 = seg * LC2; if (c0 > W2 - LC2) c0 = W2 - LC2;
        float ryv = ry[r];
        const float2* vrow = V1 + r * P1W;
        float2* arow = AB + r * ABW;
        float2 ring[K];
        float2 acc = make_float2(0.f, 0.f);
#pragma unroll
        for (int j = 0; j < K; ++j) { float2 v = vrow[c0 + j]; ring[j] = v; acc = p_add(acc, v); }
#pragma unroll
        for (int k = 0; k < LC2; ++k) {
            if (k > 0) {
                float2 vi = vrow[c0 + k + K - 1];
                float2 vo = ring[(k - 1) % K];
                ring[(k - 1) % K] = vi;
                acc = p_slide(acc, vi, vo);
            }
            float inv = ryv * rx[c0 + k];
            float m = acc.x * inv, q = acc.y * inv;
            float var = fmaf(-m, m, q);
            float rr = __frcp_rn(var + EPS);
            arow[c0 + k] = make_float2(var * rr, m * (EPS * rr));
        }
    }
    __syncthreads();

    // P3: horizontal box of (A,b) -> G (fixed LC3 trips, ring)
    for (int item = tid; item < H1R * NSEG3; item += NT) {
        int r = item % H1R, seg = item / H1R;
        int c0 = seg * LC3; if (c0 > T - LC3) c0 = T - LC3;
        const float2* arow = AB + r * ABW;
        float2* grow = G + r * GW;
        float2 ring[K];
        float2 acc = make_float2(0.f, 0.f);
#pragma unroll
        for (int j = 0; j < K; ++j) { float2 v = arow[c0 + j]; ring[j] = v; acc = p_add(acc, v); }
        grow[c0] = acc;
#pragma unroll
        for (int k = 1; k < LC3; ++k) {
            float2 vi = arow[c0 + k + K - 1];
            float2 vo = ring[(k - 1) % K];
            ring[(k - 1) % K] = vi;
            acc = p_slide(acc, vi, vo);
            grow[c0 + k] = acc;
        }
    }
    __syncthreads();

    // P4: vertical box of G + epilogue (fixed LR4 trips; head-cache sub-side)
    for (int item = tid; item < T * NSEG4; item += NT) {
        int c = item % T, seg = item / T;
        int r0 = seg * LR4; if (r0 > T - LR4) r0 = T - LR4;
        int gx = gx0 + c;
        float2 head[LR4 - 1];
        float2 acc = make_float2(0.f, 0.f);
#pragma unroll
        for (int j = 0; j < K; ++j) {
            float2 v = G[(r0 + j) * GW + c];
            if (j < LR4 - 1) head[j] = v;
            acc = p_add(acc, v);
        }
#pragma unroll 2
        for (int k = 0; k < LR4; ++k) {
            if (k > 0) {
                float2 vi = G[(r0 + k - 1 + K) * GW + c];
                acc = p_slide(acc, vi, head[k - 1]);
            }
            int gy = gy0 + r0 + k;
            if (gy < HH && gx < WW) {
                int g = gb + gy * WW + gx;
                float a = 3.f * acc.x, cc = 3.f * acc.y;
                if (STAGE == 2) {
                    float2 p = g_P1[g];
                    g_P2[g] = make_float2(a * p.x, fmaf(a, p.y, cc));
                } else {
                    float2 p1 = g_P1[g], p2 = g_P2[g];
                    float A3 = a * p2.x, C3 = fmaf(a, p2.y, cc);
                    float al0 = 1.f - p1.x, be0 = -p1.y;
                    float al1 = p1.x - p2.x, be1 = p1.y - p2.y;
                    float al2 = p2.x - A3,   be2 = p2.y - C3;
                    const float* xp = x + (size_t)b * 3 * HW + gy * WW + gx;
                    float x0 = xp[0], x1 = xp[HW], x2 = xp[2 * HW];
                    float d0 = fmaf(al0, x0, be0), d1 = fmaf(al0, x1, be0), d2 = fmaf(al0, x2, be0);
                    float d3 = fmaf(al1, x0, be1), d4 = fmaf(al1, x1, be1), d5 = fmaf(al1, x2, be1);
                    float d6 = fmaf(al2, x0, be2), d7 = fmaf(al2, x1, be2), d8 = fmaf(al2, x2, be2);
#pragma unroll
                    for (int o = 0; o < 3; ++o) {
                        float acc2 =     cw[o * 9 + 0] * d0;
                        acc2 = fmaf(cw[o * 9 + 1], d1, acc2);
                        acc2 = fmaf(cw[o * 9 + 2], d2, acc2);
                        acc2 = fmaf(cw[o * 9 + 3], d3, acc2);
                        acc2 = fmaf(cw[o * 9 + 4], d4, acc2);
                        acc2 = fmaf(cw[o * 9 + 5], d5, acc2);
                        acc2 = fmaf(cw[o * 9 + 6], d6, acc2);
                        acc2 = fmaf(cw[o * 9 + 7], d7, acc2);
                        acc2 = fmaf(cw[o * 9 + 8], d8, acc2);
                        out[(size_t)(b * 3 + o) * HW + (size_t)gy * WW + gx] = acc2;
                    }
                }
            }
        }
    }
}

static constexpr int s1_smem() {
    int E1 = 66, E2 = 68;
    return (E2 * (E2 + 1) + E2 * (E1 + 1)) * 8 + E1 * 4;
}
static constexpr int gf_smem(int R, int T) {
    int H1R = T + 2 * R, W2 = T + 2 * R, W1 = T + 4 * R;
    return (H1R * (W1 + 1) + H1R * (W2 + 1)) * 8 + (W2 + H1R) * 4;
}

extern "C" void kernel_launch(void* const* d_in, const int* in_sizes, int n_in,
                              void* d_out, int out_size) {
    const float* x  = (const float*)d_in[0];
    const float* wg = (const float*)d_in[1];
    float* out = (float*)d_out;

    cudaMemcpyToSymbolAsync(cw, wg, 27 * sizeof(float), 0, cudaMemcpyDeviceToDevice);

    constexpr int SB1 = s1_smem();        // ~72.5 KB -> 3 blocks/SM
    constexpr int SB2 = gf_smem(3, 64);   // ~81.5 KB -> 2 blocks/SM
    constexpr int SB3 = gf_smem(7, 64);   // ~105.4 KB -> 2 blocks/SM
    cudaFuncSetAttribute((const void*)stage1_kernel,          cudaFuncAttributeMaxDynamicSharedMemorySize, SB1);
    cudaFuncSetAttribute((const void*)gf_kernel<3, 2, 64, 2>, cudaFuncAttributeMaxDynamicSharedMemorySize, SB2);
    cudaFuncSetAttribute((const void*)gf_kernel<7, 3, 64, 2>, cudaFuncAttributeMaxDynamicSharedMemorySize, SB3);

    dim3 g64(WW / 64, HH / 64, BB);

    stage1_kernel<<<g64, NT, SB1>>>(x);
    gf_kernel<3, 2, 64, 2><<<g64, NT, SB2>>>(x, out);
    gf_kernel<7, 3, 64, 2><<<g64, NT, SB3>>>(x, out);
}

// round 17
// speedup vs baseline: 1.0249x; 1.0249x over previous
#include <cuda_runtime.h>

// Problem shape (fixed): x_hr (16,3,512,512) f32, w1 (3,9) f32.
#define BB 16
#define HH 512
#define WW 512
#define HW (HH*WW)
#define NPIX (BB*HW)
#define NT 512

// Per-pixel scratch maps (__device__ globals allowed).
__device__ float2 g_uv[NPIX];   // (sum_c x, sum_c x^2)
__device__ float2 g_P1[NPIX];   // cumulative affine after stage 1: F1 = P.x*x + P.y
__device__ float2 g_P2[NPIX];   // cumulative affine after stage 2
__constant__ float cw[27];      // 1x1 conv weights (3x9)

// ---------------- stage 1: fully staged, fixed-trip ring slides ----------------
__global__ void __launch_bounds__(NT, 3) stage1_kernel(const float* __restrict__ x) {
    constexpr int R = 1, T = 64;
    constexpr int K  = 2 * R + 1;
    constexpr int E1 = T + 2 * R;    // 66
    constexpr int E2 = T + 4 * R;    // 68
    constexpr int SP = E2 + 1;
    constexpr int HP = E1 + 1;
    constexpr float EPS = 0.16f;

    constexpr int NS1 = NT / E2, LS1 = (E1 + NS1 - 1) / NS1;
    constexpr int NV1 = NT / E1, LV1 = (E1 + NV1 - 1) / NV1;
    constexpr int NS2 = NT / E1, LS2 = (T + NS2 - 1) / NS2;
    constexpr int NV2 = NT / T,  LV2 = T / NV2;

    extern __shared__ float2 sm2[];
    float2* SS = sm2;                    // E2 x SP (s), later (A,b)
    float2* Hs = SS + E2 * SP;           // E2 x HP
    float*  ry = (float*)(Hs + E2 * HP); // E1 row factors

    const int tid = threadIdx.x;
    const int gx0 = blockIdx.x * T, gy0 = blockIdx.y * T;
    const int b = blockIdx.z, gb = b * HW;

    if (tid < E1) {
        int gy = gy0 - R + tid;
        float r = 0.f;
        if ((unsigned)gy < (unsigned)HH)
            r = __frcp_rn((float)(min(gy + R, HH - 1) - max(gy - R, 0) + 1));
        ry[tid] = r;
    }

    // P0: load x once; build s = (sum_c x, sum_c x^2); persist uv for interior
    for (int idx = tid; idx < E2 * E2; idx += NT) {
        int iy = idx / E2, ix = idx - iy * E2;
        int gy = gy0 - 2 * R + iy, gx = gx0 - 2 * R + ix;
        float2 s = make_float2(0.f, 0.f);
        if ((unsigned)gy < (unsigned)HH && (unsigned)gx < (unsigned)WW) {
            const float* xb = x + (size_t)b * 3 * HW + gy * WW + gx;
            float x0 = xb[0], x1 = xb[HW], x2 = xb[2 * HW];
            s.x = x0 + x1 + x2;
            s.y = x0 * x0 + x1 * x1 + x2 * x2;
            if (iy >= 2 * R && iy < 2 * R + T && ix >= 2 * R && ix < 2 * R + T)
                g_uv[gb + gy * WW + gx] = s;
        }
        SS[iy * SP + ix] = s;
    }
    __syncthreads();

    // P1: horizontal box (fixed LS1 trips, ring sub-side)
    for (int item = tid; item < E2 * NS1; item += NT) {
        int r = item % E2, seg = item / E2;
        int c0 = seg * LS1; if (c0 > E1 - LS1) c0 = E1 - LS1;
        const float2* p = SS + r * SP;
        float2* o = Hs + r * HP;
        float2 ring[K];
        float ax = 0.f, ay = 0.f;
#pragma unroll
        for (int j = 0; j < K; ++j) { float2 v = p[c0 + j]; ring[j] = v; ax += v.x; ay += v.y; }
        o[c0] = make_float2(ax, ay);
#pragma unroll
        for (int k = 1; k < LS1; ++k) {
            float2 vi = p[c0 + k + K - 1];
            float2 vo = ring[(k - 1) % K];
            ring[(k - 1) % K] = vi;
            ax += vi.x - vo.x; ay += vi.y - vo.y;
            o[c0 + k] = make_float2(ax, ay);
        }
    }
    __syncthreads();

    // P2: vertical box + pointwise (A,b) -> SS (fixed LV1 trips, ring)
    for (int item = tid; item < E1 * NV1; item += NT) {
        int c = item % E1, seg = item / E1;
        int r0 = seg * LV1; if (r0 > E1 - LV1) r0 = E1 - LV1;
        int gx = gx0 - R + c;
        float rx = 0.f;
        if ((unsigned)gx < (unsigned)WW)
            rx = __frcp_rn(3.f * (float)(min(gx + R, WW - 1) - max(gx - R, 0) + 1));
        float2 ring[K];
        float a1 = 0.f, a2 = 0.f;
#pragma unroll
        for (int j = 0; j < K; ++j) { float2 v = Hs[(r0 + j) * HP + c]; ring[j] = v; a1 += v.x; a2 += v.y; }
#pragma unroll
        for (int k = 0; k < LV1; ++k) {
            if (k > 0) {
                float2 vi = Hs[(r0 + k + K - 1) * HP + c];
                float2 vo = ring[(k - 1) % K];
                ring[(k - 1) % K] = vi;
                a1 += vi.x - vo.x; a2 += vi.y - vo.y;
            }
            float inv = ry[r0 + k] * rx;
            float m = a1 * inv, q = a2 * inv;
            float var = fmaf(-m, m, q);
            float rr = __frcp_rn(var + EPS);
            SS[(r0 + k) * SP + c] = make_float2(var * rr, m * (EPS * rr));
        }
    }
    __syncthreads();

    // P3: horizontal box of (A,b) (fixed LS2 trips, ring)
    for (int item = tid; item < E1 * NS2; item += NT) {
        int r = item % E1, seg = item / E1;
        int c0 = seg * LS2; if (c0 > T - LS2) c0 = T - LS2;
        const float2* p = SS + r * SP;
        float2* o = Hs + r * HP;
        float2 ring[K];
        float ax = 0.f, ay = 0.f;
#pragma unroll
        for (int j = 0; j < K; ++j) { float2 v = p[c0 + j]; ring[j] = v; ax += v.x; ay += v.y; }
        o[c0] = make_float2(ax, ay);
#pragma unroll
        for (int k = 1; k < LS2; ++k) {
            float2 vi = p[c0 + k + K - 1];
            float2 vo = ring[(k - 1) % K];
            ring[(k - 1) % K] = vi;
            ax += vi.x - vo.x; ay += vi.y - vo.y;
            o[c0 + k] = make_float2(ax, ay);
        }
    }
    __syncthreads();

    // P4: vertical box + epilogue -> g_P1 (fixed LV2 trips, ring)
    for (int item = tid; item < T * NV2; item += NT) {
        int c = item % T, seg = item / T;
        int r0 = seg * LV2;
        int gx = gx0 + c;
        float2 ring[K];
        float a1 = 0.f, a2 = 0.f;
#pragma unroll
        for (int j = 0; j < K; ++j) { float2 v = Hs[(r0 + j) * HP + c]; ring[j] = v; a1 += v.x; a2 += v.y; }
#pragma unroll
        for (int k = 0; k < LV2; ++k) {
            if (k > 0) {
                float2 vi = Hs[(r0 + k + K - 1) * HP + c];
                float2 vo = ring[(k - 1) % K];
                ring[(k - 1) % K] = vi;
                a1 += vi.x - vo.x; a2 += vi.y - vo.y;
            }
            g_P1[gb + (gy0 + r0 + k) * WW + gx] = make_float2(3.f * a1, 3.f * a2);
        }
    }
}

// Channel-sum eval from (u,v) + cumulative affine (two LDG.64).
template <int STAGE>
__device__ __forceinline__ float2 s_eval(int gb, int gy, int gx, bool vx) {
    if (!vx || (unsigned)gy >= (unsigned)HH) return make_float2(0.f, 0.f);
    int g = gb + gy * WW + gx;
    float2 uv = g_uv[g];
    float2 P  = (STAGE == 2) ? g_P1[g] : g_P2[g];
    return make_float2(fmaf(P.x, uv.x, 3.f * P.y),
                       fmaf(P.x * P.x, uv.y,
                            fmaf(2.f * P.x * P.y, uv.x, 3.f * P.y * P.y)));
}

// ---------------- stages 2 & 3: 4 phases; rings everywhere ----------------
// T = 64 divides 512 exactly -> P4 needs no bounds guard and no r0 clamp.
template <int R, int STAGE, int T, int MINB>
__global__ void __launch_bounds__(NT, MINB) gf_kernel(const float* __restrict__ x,
                                                      float* __restrict__ out) {
    constexpr int K   = 2 * R + 1;
    constexpr int H1R = T + 2 * R;
    constexpr int W2  = T + 2 * R;
    constexpr int W1  = T + 4 * R;
    constexpr int P1W = W1 + 1;
    constexpr int ABW = W2 + 1;
    constexpr int GW  = T + 1;
    constexpr float EPS = (STAGE == 2) ? 0.04f : 0.01f;

    constexpr int NSEG1 = NT / W1,  LR1 = (H1R + NSEG1 - 1) / NSEG1;
    constexpr int NSEG2 = NT / H1R, LC2 = (W2 + NSEG2 - 1) / NSEG2;
    constexpr int NSEG3 = NT / H1R, LC3 = (T + NSEG3 - 1) / NSEG3;
    constexpr int NSEG4 = NT / T,   LR4 = T / NSEG4;
    static_assert(H1R >= LR1 && W2 >= LC2 && T >= LC3, "clamp ok");
    static_assert(T % NSEG4 == 0, "P4 exact tiling");

    extern __shared__ float2 sm2[];
    float2* V1 = sm2;                    // H1R x P1W
    float2* AB = V1 + H1R * P1W;         // H1R x ABW
    float2* G  = V1;                     // aliases dead V1 after P2
    float*  rx = (float*)(AB + H1R * ABW);
    float*  ry = rx + W2;

    const int tid = threadIdx.x;
    const int gx0 = blockIdx.x * T, gy0 = blockIdx.y * T;
    const int b = blockIdx.z, gb = b * HW;

    if (tid < W2) {
        int gx = gx0 - R + tid;
        float v = 0.f;
        if ((unsigned)gx < (unsigned)WW)
            v = __frcp_rn((float)(min(gx + R, WW - 1) - max(gx - R, 0) + 1));
        rx[tid] = v;
    }
    int t2 = tid - 128;
    if (t2 >= 0 && t2 < H1R) {
        int gy = gy0 - R + t2;
        float v = 0.f;
        if ((unsigned)gy < (unsigned)HH)
            v = __frcp_rn(3.f * (float)(min(gy + R, HH - 1) - max(gy - R, 0) + 1));
        ry[t2] = v;
    }

    // P1: vertical box of s off global, register-ring slide (fixed LR1 trips)
    for (int item = tid; item < W1 * NSEG1; item += NT) {
        int c = item % W1, seg = item / W1;
        int r0 = seg * LR1; if (r0 > H1R - LR1) r0 = H1R - LR1;
        int gx = gx0 - 2 * R + c;
        bool vx = (unsigned)gx < (unsigned)WW;
        int ybase = gy0 - 2 * R + r0;
        float2 ring[K];
        float a1 = 0.f, a2 = 0.f;
#pragma unroll
        for (int j = 0; j < K; ++j) {
            float2 s = s_eval<STAGE>(gb, ybase + j, gx, vx);
            ring[j] = s;
            a1 += s.x; a2 += s.y;
        }
        V1[r0 * P1W + c] = make_float2(a1, a2);
#pragma unroll
        for (int k = 1; k < LR1; ++k) {
            float2 sa = s_eval<STAGE>(gb, ybase + k + K - 1, gx, vx);
            float2 sb = ring[(k - 1) % K];
            ring[(k - 1) % K] = sa;
            a1 += sa.x - sb.x; a2 += sa.y - sb.y;
            V1[(r0 + k) * P1W + c] = make_float2(a1, a2);
        }
    }
    __syncthreads();

    // P2: horizontal box + pointwise (A,b) (fixed LC2 trips, ring)
    for (int item = tid; item < H1R * NSEG2; item += NT) {
        int r = item % H1R, seg = item / H1R;
        int c0 = seg * LC2; if (c0 > W2 - LC2) c0 = W2 - LC2;
        float ryv = ry[r];
        const float2* vrow = V1 + r * P1W;
        float2* arow = AB + r * ABW;
        float2 ring[K];
        float a1 = 0.f, a2 = 0.f;
#pragma unroll
        for (int j = 0; j < K; ++j) { float2 v = vrow[c0 + j]; ring[j] = v; a1 += v.x; a2 += v.y; }
#pragma unroll
        for (int k = 0; k < LC2; ++k) {
            if (k > 0) {
                float2 vi = vrow[c0 + k + K - 1];
                float2 vo = ring[(k - 1) % K];
                ring[(k - 1) % K] = vi;
                a1 += vi.x - vo.x; a2 += vi.y - vo.y;
            }
            float inv = ryv * rx[c0 + k];
            float m = a1 * inv, q = a2 * inv;
            float var = fmaf(-m, m, q);
            float rr = __frcp_rn(var + EPS);
            arow[c0 + k] = make_float2(var * rr, m * (EPS * rr));
        }
    }
    __syncthreads();

    // P3: horizontal box of (A,b) -> G (fixed LC3 trips, ring)
    for (int item = tid; item < H1R * NSEG3; item += NT) {
        int r = item % H1R, seg = item / H1R;
        int c0 = seg * LC3; if (c0 > T - LC3) c0 = T - LC3;
        const float2* arow = AB + r * ABW;
        float2* grow = G + r * GW;
        float2 ring[K];
        float a1 = 0.f, a2 = 0.f;
#pragma unroll
        for (int j = 0; j < K; ++j) { float2 v = arow[c0 + j]; ring[j] = v; a1 += v.x; a2 += v.y; }
        grow[c0] = make_float2(a1, a2);
#pragma unroll
        for (int k = 1; k < LC3; ++k) {
            float2 vi = arow[c0 + k + K - 1];
            float2 vo = ring[(k - 1) % K];
            ring[(k - 1) % K] = vi;
            a1 += vi.x - vo.x; a2 += vi.y - vo.y;
            grow[c0 + k] = make_float2(a1, a2);
        }
    }
    __syncthreads();

    // P4: vertical box of G + epilogue (exact tiling -> no clamps, no guards)
    for (int item = tid; item < T * NSEG4; item += NT) {
        int c = item % T, seg = item / T;
        int r0 = seg * LR4;
        int gx = gx0 + c;
        float a1 = 0.f, a2 = 0.f;
#pragma unroll
        for (int j = 0; j < K; ++j) { float2 v = G[(r0 + j) * GW + c]; a1 += v.x; a2 += v.y; }
#pragma unroll 2
        for (int k = 0; k < LR4; ++k) {
            if (k > 0) {
                float2 vi = G[(r0 + k - 1 + K) * GW + c], vo = G[(r0 + k - 1) * GW + c];
                a1 += vi.x - vo.x; a2 += vi.y - vo.y;
            }
            int gy = gy0 + r0 + k;
            int g = gb + gy * WW + gx;
            float a = 3.f * a1, cc = 3.f * a2;
            if (STAGE == 2) {
                float2 p = g_P1[g];
                g_P2[g] = make_float2(a * p.x, fmaf(a, p.y, cc));
            } else {
                float2 p1 = g_P1[g], p2 = g_P2[g];
                float A3 = a * p2.x, C3 = fmaf(a, p2.y, cc);
                float al0 = 1.f - p1.x, be0 = -p1.y;
                float al1 = p1.x - p2.x, be1 = p1.y - p2.y;
                float al2 = p2.x - A3,   be2 = p2.y - C3;
                const float* xp = x + (size_t)b * 3 * HW + gy * WW + gx;
                float x0 = xp[0], x1 = xp[HW], x2 = xp[2 * HW];
                float d0 = fmaf(al0, x0, be0), d1 = fmaf(al0, x1, be0), d2 = fmaf(al0, x2, be0);
                float d3 = fmaf(al1, x0, be1), d4 = fmaf(al1, x1, be1), d5 = fmaf(al1, x2, be1);
                float d6 = fmaf(al2, x0, be2), d7 = fmaf(al2, x1, be2), d8 = fmaf(al2, x2, be2);
#pragma unroll
                for (int o = 0; o < 3; ++o) {
                    float acc =      cw[o * 9 + 0] * d0;
                    acc = fmaf(cw[o * 9 + 1], d1, acc);
                    acc = fmaf(cw[o * 9 + 2], d2, acc);
                    acc = fmaf(cw[o * 9 + 3], d3, acc);
                    acc = fmaf(cw[o * 9 + 4], d4, acc);
                    acc = fmaf(cw[o * 9 + 5], d5, acc);
                    acc = fmaf(cw[o * 9 + 6], d6, acc);
                    acc = fmaf(cw[o * 9 + 7], d7, acc);
                    acc = fmaf(cw[o * 9 + 8], d8, acc);
                    out[(size_t)(b * 3 + o) * HW + (size_t)gy * WW + gx] = acc;
                }
            }
        }
    }
}

static constexpr int s1_smem() {
    int E1 = 66, E2 = 68;
    return (E2 * (E2 + 1) + E2 * (E1 + 1)) * 8 + E1 * 4;
}
static constexpr int gf_smem(int R, int T) {
    int H1R = T + 2 * R, W2 = T + 2 * R, W1 = T + 4 * R;
    return (H1R * (W1 + 1) + H1R * (W2 + 1)) * 8 + (W2 + H1R) * 4;
}

extern "C" void kernel_launch(void* const* d_in, const int* in_sizes, int n_in,
                              void* d_out, int out_size) {
    const float* x  = (const float*)d_in[0];
    const float* wg = (const float*)d_in[1];
    float* out = (float*)d_out;

    cudaMemcpyToSymbolAsync(cw, wg, 27 * sizeof(float), 0, cudaMemcpyDeviceToDevice);

    constexpr int SB1 = s1_smem();        // ~72.5 KB -> 3 blocks/SM
    constexpr int SB2 = gf_smem(3, 64);   // ~81.5 KB -> 2 blocks/SM
    constexpr int SB3 = gf_smem(7, 64);   // ~105.4 KB -> 2 blocks/SM
    cudaFuncSetAttribute((const void*)stage1_kernel,          cudaFuncAttributeMaxDynamicSharedMemorySize, SB1);
    cudaFuncSetAttribute((const void*)gf_kernel<3, 2, 64, 2>, cudaFuncAttributeMaxDynamicSharedMemorySize, SB2);
    cudaFuncSetAttribute((const void*)gf_kernel<7, 3, 64, 2>, cudaFuncAttributeMaxDynamicSharedMemorySize, SB3);

    dim3 g64(WW / 64, HH / 64, BB);

    stage1_kernel<<<g64, NT, SB1>>>(x);
    gf_kernel<3, 2, 64, 2><<<g64, NT, SB2>>>(x, out);
    gf_kernel<7, 3, 64, 2><<<g64, NT, SB3>>>(x, out);
}